// round 17
// baseline (speedup 1.0000x reference)
#include <cuda_runtime.h>

// SpatialTransformer: out = trilinear_sample(src, identity_grid + flow), border clamp.
// src:  [1,1,160,192,160] f32   d_in[0]
// flow: [1,3,160,192,160] f32   d_in[1]  (channel-planar: d,h,w displacement)
// grid: identity meshgrid       d_in[2]  (IGNORED - recomputed from indices)
// out:  [1,1,160,192,160] f32
//
// Math collapse (verified, rel_err 2.6e-5):
//   ux = (w + flow[2]) * W/(W-1) - 0.5 ; clamp [0, W-1]; trilinear w/ clamped +1.
//
// Settled model (R6..R16): latency-bound divergent-gather kernel; L1 sector
// throughput ceiling ~35us; plateau 48us because 32 warps/SM x 8 chains
// underfeeds L1 (71%). Register cap (55, of which 24 = idle flow values)
// limits warps. R17: stage flow in SMEM as per-thread private scratch
// (no sync needed, conflict-free, keeps single front-batched latency
// exposure) -> regs ~38 -> __launch_bounds__(256,6) -> 48 warps/SM (+50% MLP).

#define DD 160
#define HH 192
#define WW 160
#define PLANE (HH * WW)
#define NN (DD * HH * WW)
#define ZB 8   // z-batch per thread

__global__ __launch_bounds__(256, 6) void st_warp_tile_sm_kernel(
    const float* __restrict__ src,
    const float* __restrict__ flow,
    float* __restrict__ out)
{
    // per-thread private flow scratch in smem: [channel][k][tid], conflict-free
    __shared__ float fsm[3 * ZB * 256];

    const int tidl = threadIdx.y * 32 + threadIdx.x;

    // 3D tile: 32 (x) x 8 (h) x ZB (z) voxels per block, 256 threads
    const int w  = blockIdx.x * 32 + threadIdx.x;
    const int h  = blockIdx.y * 8 + threadIdx.y;
    const int d0 = blockIdx.z * ZB;
    const int base = (d0 * HH + h) * WW + w;

    const float sx = (float)WW / (float)(WW - 1);
    const float sy = (float)HH / (float)(HH - 1);
    const float sz = (float)DD / (float)(DD - 1);

    // front-batched flow loads -> smem scratch (one latency exposure; STS
    // drains as LDG data arrives; each thread touches only its own slots)
#pragma unroll
    for (int k = 0; k < ZB; k++) {
        const int idx = base + k * PLANE;
        fsm[(0 * ZB + k) * 256 + tidl] = __ldcs(flow + idx);            // D-disp
        fsm[(1 * ZB + k) * 256 + tidl] = __ldcs(flow + NN + idx);       // H-disp
        fsm[(2 * ZB + k) * 256 + tidl] = __ldcs(flow + 2 * NN + idx);   // W-disp
    }

#pragma unroll
    for (int k = 0; k < ZB; k++) {
        const int d = d0 + k;

        const float fd = fsm[(0 * ZB + k) * 256 + tidl];
        const float fh = fsm[(1 * ZB + k) * 256 + tidl];
        const float fw = fsm[(2 * ZB + k) * 256 + tidl];

        float ux = ((float)w + fw) * sx - 0.5f;
        float uy = ((float)h + fh) * sy - 0.5f;
        float uz = ((float)d + fd) * sz - 0.5f;

        ux = fminf(fmaxf(ux, 0.0f), (float)(WW - 1));
        uy = fminf(fmaxf(uy, 0.0f), (float)(HH - 1));
        uz = fminf(fmaxf(uz, 0.0f), (float)(DD - 1));

        // coords >= 0 -> truncation == floor
        const int x0 = (int)ux;
        const int y0 = (int)uy;
        const int z0 = (int)uz;
        const float ax = ux - (float)x0;
        const float ay = uy - (float)y0;
        const float az = uz - (float)z0;

        const int x1 = min(x0 + 1, WW - 1);
        const int y1 = min(y0 + 1, HH - 1);
        const int z1 = min(z0 + 1, DD - 1);

        const int x0a = x0 & ~1;            // 8B-aligned pair start
        const bool odd = (x0 & 1) != 0;

        const int zy00 = (z0 * HH + y0) * WW;
        const int zy01 = (z0 * HH + y1) * WW;
        const int zy10 = (z1 * HH + y0) * WW;
        const int zy11 = (z1 * HH + y1) * WW;

        const float2 v00 = __ldg((const float2*)(src + zy00 + x0a));
        const float2 v01 = __ldg((const float2*)(src + zy01 + x0a));
        const float2 v10 = __ldg((const float2*)(src + zy10 + x0a));
        const float2 v11 = __ldg((const float2*)(src + zy11 + x0a));

        // predicated fix-up loads for odd x0 (pair straddles float2 boundary)
        float e00 = v00.y, e01 = v01.y, e10 = v10.y, e11 = v11.y;
        if (odd) e00 = __ldg(src + zy00 + x1);
        if (odd) e01 = __ldg(src + zy01 + x1);
        if (odd) e10 = __ldg(src + zy10 + x1);
        if (odd) e11 = __ldg(src + zy11 + x1);

        const float l00 = odd ? v00.y : v00.x;
        const float l01 = odd ? v01.y : v01.x;
        const float l10 = odd ? v10.y : v10.x;
        const float l11 = odd ? v11.y : v11.x;

        const float c00 = fmaf(ax, e00 - l00, l00);
        const float c01 = fmaf(ax, e01 - l01, l01);
        const float c10 = fmaf(ax, e10 - l10, l10);
        const float c11 = fmaf(ax, e11 - l11, l11);

        const float c0 = fmaf(ay, c01 - c00, c00);
        const float c1 = fmaf(ay, c11 - c10, c10);
        // streaming store: no L1 allocation for write-once output
        __stcs(out + base + k * PLANE, fmaf(az, c1 - c0, c0));
    }
}

extern "C" void kernel_launch(void* const* d_in, const int* in_sizes, int n_in,
                              void* d_out, int out_size)
{
    const float* src  = (const float*)d_in[0];
    const float* flow = (const float*)d_in[1];
    // d_in[2] (identity grid) intentionally unused — recomputed from indices.
    float* out = (float*)d_out;

    dim3 block(32, 8, 1);
    dim3 grid(WW / 32, HH / 8, DD / ZB);   // 5 x 24 x 20 = 2400 blocks
    st_warp_tile_sm_kernel<<<grid, block>>>(src, flow, out);
}